// round 10
// baseline (speedup 1.0000x reference)
#include <cuda_runtime.h>
#include <math_constants.h>
#include <cstdint>

#define BN    8
#define BC    256
#define BNF   16
#define BWH   784            // 28*28
#define CSTR  (BNF*BWH)      // 12544 floats between channels
#define CSTR4 (CSTR/4)       // 3136 float4
#define NV4   (BWH/4)        // 196 float4 per wh-row
#define NTILE (BN*BNF)       // 128 tiles
#define NK    8              // channel-groups (sibling CTAs) per tile
#define CPC   32             // channels per CTA
#define NTHR  256
#define SMEM_B (CPC * BWH * 4)   // 100,352 B dynamic smem

// scratch: per-(tile,group) partial channel-dot; fully overwritten each run
__device__ float         d_part[NTILE][NK][BWH];   // 3.2 MB
__device__ unsigned int  d_cnt[NTILE];             // monotonic arrival counters

__global__ __launch_bounds__(NTHR)
void mfla_fused_kernel(const float* __restrict__ l,
                       const float* __restrict__ g,
                       const float* __restrict__ w,
                       float* __restrict__ outc,   // [N,NF,W,H]
                       float* __restrict__ outg)   // [N,C,NF]
{
    extern __shared__ __align__(16) float cache[];     // [32][784] my channels
    __shared__ __align__(16) float sc[BWH];            // exp values
    __shared__ float sw[CPC];
    __shared__ float red[NK];
    __shared__ float s_gdot, s_inv;

    const int tid  = threadIdx.x;
    const int tile = blockIdx.x >> 3;     // n*16 + f
    const int k    = blockIdx.x & 7;      // channel group
    const int n    = tile >> 4;
    const int f    = tile & 15;
    const int c0   = k * CPC;

    const float4* lb4 = reinterpret_cast<const float4*>(
        l + ((size_t)(n * BC + c0) * BNF + f) * BWH);
    float4* cache4 = reinterpret_cast<float4*>(cache);

    // ---- gdot = sum over ALL 256 channels (redundant per CTA); sw = my weights ----
    {
        float p = g[n * BC + tid] * w[tid];
        if (tid < CPC) sw[tid] = w[c0 + tid];
        #pragma unroll
        for (int o = 16; o; o >>= 1) p += __shfl_xor_sync(0xffffffffu, p, o);
        if ((tid & 31) == 0) red[tid >> 5] = p;
        __syncthreads();
        if (tid < NK) {
            float v = red[tid];
            #pragma unroll
            for (int o = 4; o; o >>= 1) v += __shfl_xor_sync(0xffu, v, o);
            if (tid == 0) s_gdot = v;
        }
    }

    // ---- Phase 1: pure copy of my 32 channels into smem (single global read of l) ----
    #pragma unroll 4
    for (int idx = tid; idx < CPC * NV4; idx += NTHR) {
        const int c = idx / NV4;
        const int i = idx - c * NV4;
        cache4[idx] = lb4[(size_t)c * CSTR4 + i];
    }
    __syncthreads();

    // ---- Phase 2: my partial channel-dot from smem -> scratch ----
    if (tid < NV4) {
        float4 a = make_float4(0.f, 0.f, 0.f, 0.f);
        #pragma unroll
        for (int c = 0; c < CPC; ++c) {
            float4 v = cache4[c * NV4 + tid];
            float wv = sw[c];
            a.x = fmaf(v.x, wv, a.x);
            a.y = fmaf(v.y, wv, a.y);
            a.z = fmaf(v.z, wv, a.z);
            a.w = fmaf(v.w, wv, a.w);
        }
        reinterpret_cast<float4*>(&d_part[tile][k][0])[tid] = a;
    }
    __threadfence();      // make my partial visible GPU-wide before arriving
    __syncthreads();

    // ---- software barrier across the 8 sibling CTAs of this tile ----
    if (tid == 0) {
        unsigned int old = atomicAdd(&d_cnt[tile], 1u);
        const unsigned int target = (old & ~7u) + 8u;   // replay-safe monotonic
        while (atomicAdd(&d_cnt[tile], 0u) < target) {}
    }
    __syncthreads();
    __threadfence();

    // ---- Phase 3: combine 8 partials + gdot; k==0 writes c; exp; block sum ----
    float se = 0.f;
    if (tid < NV4) {
        const float gd = s_gdot;
        float4 v = make_float4(gd, gd, gd, gd);
        #pragma unroll
        for (int r = 0; r < NK; ++r) {
            float4 p4 = __ldcg(reinterpret_cast<const float4*>(&d_part[tile][r][0]) + tid);
            v.x += p4.x; v.y += p4.y; v.z += p4.z; v.w += p4.w;
        }
        if (k == 0)
            reinterpret_cast<float4*>(outc + (size_t)tile * BWH)[tid] = v;
        float4 e = make_float4(__expf(v.x), __expf(v.y), __expf(v.z), __expf(v.w));
        reinterpret_cast<float4*>(sc)[tid] = e;
        se = (e.x + e.y) + (e.z + e.w);
    }
    #pragma unroll
    for (int o = 16; o; o >>= 1) se += __shfl_xor_sync(0xffffffffu, se, o);
    if ((tid & 31) == 0) red[tid >> 5] = se;
    __syncthreads();
    if (tid < NK) {
        float v = red[tid];
        #pragma unroll
        for (int o = 4; o; o >>= 1) v += __shfl_xor_sync(0xffu, v, o);
        if (tid == 0) s_inv = 1.0f / v;
    }
    __syncthreads();

    // ---- Phase 4: pool my 32 channels from smem: 8 warps x 4 channels ----
    {
        const int warp = tid >> 5;
        const int lane = tid & 31;
        const float inv = s_inv;
        const float4* av = reinterpret_cast<const float4*>(sc);
        const int cl = 4 * warp;             // local channel base
        float acc[4] = {0.f, 0.f, 0.f, 0.f};
        for (int i = lane; i < NV4; i += 32) {
            float4 a4 = av[i];
            #pragma unroll
            for (int kk = 0; kk < 4; ++kk) {
                float4 l4 = cache4[(cl + kk) * NV4 + i];
                acc[kk] += a4.x * l4.x + a4.y * l4.y + a4.z * l4.z + a4.w * l4.w;
            }
        }
        #pragma unroll
        for (int kk = 0; kk < 4; ++kk) {
            float a = acc[kk];
            #pragma unroll
            for (int o = 16; o; o >>= 1) a += __shfl_xor_sync(0xffffffffu, a, o);
            if (lane == 0)
                outg[((size_t)n * BC + c0 + cl + kk) * BNF + f] = a * inv;
        }
    }
}

extern "C" void kernel_launch(void* const* d_in, const int* in_sizes, int n_in,
                              void* d_out, int out_size)
{
    const float* l = (const float*)d_in[0];
    const float* g = (const float*)d_in[1];
    const float* w = (const float*)d_in[2];
    float* out  = (float*)d_out;
    float* outc = out;                              // 8*16*28*28 = 100352 floats
    float* outg = out + (size_t)BN * BNF * BWH;     // 8*256*16   = 32768 floats

    cudaFuncSetAttribute(mfla_fused_kernel,
                         cudaFuncAttributeMaxDynamicSharedMemorySize, SMEM_B);
    mfla_fused_kernel<<<NTILE * NK, NTHR, SMEM_B>>>(l, g, w, outc, outg);
}

// round 11
// speedup vs baseline: 1.7509x; 1.7509x over previous
#include <cuda_runtime.h>
#include <math_constants.h>
#include <cstdint>

#define BN    8
#define BC    256
#define BNF   16
#define BWH   784            // 28*28
#define CSTR4 3136           // float4 stride between channels
#define NV4   196            // float4 per wh-row
#define NTILE (BN*BNF)       // 128
#define NCH   14             // wh-chunks per tile
#define CF4   14             // float4 per chunk (56 wh)
#define K1THR 256
#define K2THR 256

#define SMEM_B (BC * CF4 * 16)   // 57344 B: scache4[256][14]

// scratch — fully overwritten every run (no zeroing, no atomics on data)
__device__ float d_P[NTILE][NCH][BC];      // unnormalized partial pools (1.8 MB)
__device__ float d_es[NTILE][NCH];         // partial exp-sums

// ---------------- K1: cache chunk, dot, exp, partial pool ----------------
__global__ __launch_bounds__(K1THR)
void mfla_chunk_kernel(const float* __restrict__ l,
                       const float* __restrict__ g,
                       const float* __restrict__ w,
                       float* __restrict__ outc)
{
    extern __shared__ __align__(16) float4 scache4[];   // [256][14]
    __shared__ float  sw[BC];
    __shared__ __align__(16) float4 part4[16 * CF4];    // 16 cgroups x 14 pos
    __shared__ __align__(16) float4 aexp4[CF4];         // exp(c) for this chunk
    __shared__ float  red[8];
    __shared__ float  s_gdot;

    const int tid   = threadIdx.x;
    const int tile  = blockIdx.x / NCH;      // n*16 + f
    const int chunk = blockIdx.x - tile * NCH;
    const int n     = tile >> 4;
    const int f     = tile & 15;
    const int base  = chunk * CF4;           // f4 offset within wh-row

    const float4* lb4 = reinterpret_cast<const float4*>(
        l + ((size_t)n * BC * BNF + f) * BWH);   // channel c at lb4[c*CSTR4]

    // ---- gdot over all 256 channels + weights to smem ----
    {
        float wv = w[tid];
        sw[tid] = wv;
        float p = g[n * BC + tid] * wv;
        #pragma unroll
        for (int o = 16; o; o >>= 1) p += __shfl_xor_sync(0xffffffffu, p, o);
        if ((tid & 31) == 0) red[tid >> 5] = p;
        __syncthreads();
        if (tid < 8) {
            float v = red[tid];
            #pragma unroll
            for (int o = 4; o; o >>= 1) v += __shfl_xor_sync(0xffu, v, o);
            if (tid == 0) s_gdot = v;
        }
    }

    // ---- Phase 1: copy my chunk (all 256 channels x 14 f4) into smem ----
    #pragma unroll
    for (int it = 0; it < (BC * CF4) / K1THR; ++it) {   // 14 iters
        const int idx = tid + it * K1THR;
        const int c   = idx / CF4;
        const int i   = idx - c * CF4;
        scache4[idx] = lb4[(size_t)c * CSTR4 + base + i];
    }
    __syncthreads();

    // ---- Phase 2: channel dot from smem: 16 cgroups x 14 positions ----
    if (tid < 16 * CF4) {
        const int pos = tid % CF4;
        const int cg  = tid / CF4;
        float4 a = make_float4(0.f, 0.f, 0.f, 0.f);
        #pragma unroll
        for (int cc = 0; cc < 16; ++cc) {
            const int c = cg * 16 + cc;
            float4 v = scache4[c * CF4 + pos];
            float wv = sw[c];
            a.x = fmaf(v.x, wv, a.x);
            a.y = fmaf(v.y, wv, a.y);
            a.z = fmaf(v.z, wv, a.z);
            a.w = fmaf(v.w, wv, a.w);
        }
        part4[cg * CF4 + pos] = a;
    }
    __syncthreads();

    // ---- Phase 2b: combine 16 partials, +gdot, write c, exp, partial expsum ----
    {
        float se = 0.f;
        if (tid < CF4) {
            const float gd = s_gdot;
            float4 v = make_float4(gd, gd, gd, gd);
            #pragma unroll
            for (int k = 0; k < 16; ++k) {
                float4 q = part4[k * CF4 + tid];
                v.x += q.x; v.y += q.y; v.z += q.z; v.w += q.w;
            }
            reinterpret_cast<float4*>(outc)[(size_t)tile * NV4 + base + tid] = v;
            float4 e = make_float4(__expf(v.x), __expf(v.y), __expf(v.z), __expf(v.w));
            aexp4[tid] = e;
            se = (e.x + e.y) + (e.z + e.w);
        }
        if (tid < 32) {
            #pragma unroll
            for (int o = 16; o; o >>= 1) se += __shfl_xor_sync(0xffffffffu, se, o);
            if (tid == 0) d_es[tile][chunk] = se;
        }
    }
    __syncthreads();

    // ---- Phase 3: partial pool, one channel per thread, all smem ----
    {
        const int c = tid;
        float acc = 0.f;
        #pragma unroll
        for (int i = 0; i < CF4; ++i) {
            float4 e = aexp4[i];                  // broadcast
            float4 v = scache4[c * CF4 + i];
            acc += e.x * v.x + e.y * v.y + e.z * v.z + e.w * v.w;
        }
        d_P[tile][chunk][c] = acc;                // coalesced across c
    }
}

// ---------------- K2: combine 14 partials per (tile, c), normalize ----------------
__global__ __launch_bounds__(K2THR)
void mfla_finish_kernel(float* __restrict__ outg)
{
    __shared__ float s_inv;
    const int tid  = threadIdx.x;
    const int tile = blockIdx.x;
    const int n    = tile >> 4;
    const int f    = tile & 15;

    if (tid == 0) {
        float s = 0.f;
        #pragma unroll
        for (int k = 0; k < NCH; ++k) s += d_es[tile][k];
        s_inv = 1.0f / s;
    }
    __syncthreads();

    float a = 0.f;
    #pragma unroll
    for (int k = 0; k < NCH; ++k) a += d_P[tile][k][tid];
    outg[((size_t)n * BC + tid) * BNF + f] = a * s_inv;
}

extern "C" void kernel_launch(void* const* d_in, const int* in_sizes, int n_in,
                              void* d_out, int out_size)
{
    const float* l = (const float*)d_in[0];
    const float* g = (const float*)d_in[1];
    const float* w = (const float*)d_in[2];
    float* out  = (float*)d_out;
    float* outc = out;                              // 8*16*28*28 = 100352 floats
    float* outg = out + (size_t)BN * BNF * BWH;     // 8*256*16   = 32768 floats

    cudaFuncSetAttribute(mfla_chunk_kernel,
                         cudaFuncAttributeMaxDynamicSharedMemorySize, SMEM_B);
    mfla_chunk_kernel <<<NTILE * NCH, K1THR, SMEM_B>>>(l, g, w, outc);
    mfla_finish_kernel<<<NTILE, K2THR>>>(outg);
}